// round 14
// baseline (speedup 1.0000x reference)
#include <cuda_runtime.h>

// Depthwise 3x3 conv, stride 1, VALID, fp32.
// x: (16, 64, 512, 512), weight: (64, 3, 3), out: (16, 64, 510, 510)

#define CCH    64
#define HH     512
#define WW     512
#define OHT    510
#define OWD    510
#define ROWS   30     // output rows per CTA (17 * 30 = 510)
#define NTILES 17

__global__ __launch_bounds__(128, 13)   // 13 CTAs/SM needs 38 regs (achieved in R3 on this body)
void dwconv3x3_kernel(const float* __restrict__ x,
                      const float* __restrict__ wgt,
                      float* __restrict__ out)
{
    const int tile = blockIdx.x;          // 0..16 (fast-varying: same-plane tiles co-wave)
    const int nc   = blockIdx.y;          // n*64 + c
    const int c    = nc & (CCH - 1);

    const float* xp = x   + (size_t)nc * HH * WW;
    float*       op = out + (size_t)nc * OHT * OWD;

    float wt[9];
#pragma unroll
    for (int i = 0; i < 9; i++) wt[i] = __ldg(wgt + c * 9 + i);

    const int  tid   = threadIdx.x;       // 0..127
    const int  x0    = tid * 4;           // output cols x0..x0+3
    const bool hi_ok = (tid < 127);       // tid 127: cols 510/511 invalid, halo OOB
    const int  y0    = tile * ROWS;

    if (!(tile & 1)) {
        // ================= even tiles: sweep top -> bottom =================
        float4 a0, a1, a2;
        float2 b0, b1, b2;
        {
            const float* r = xp + (size_t)y0 * WW + x0;
            a0 = *(const float4*)(r);
            a1 = *(const float4*)(r + WW);
            a2 = *(const float4*)(r + 2 * WW);
            if (hi_ok) {
                b0 = *(const float2*)(r + 4);
                b1 = *(const float2*)(r + WW + 4);
                b2 = *(const float2*)(r + 2 * WW + 4);
            } else {
                b0 = b1 = b2 = make_float2(0.f, 0.f);
            }
        }

        // For yy < ROWS-1 the prefetch row y0+yy+3 <= y0+31 <= 511 is ALWAYS
        // in-bounds (y0 <= 480) -> clamp-free hot loop; last iteration peeled
        // below with no prefetch.
        const float* rp = xp + (size_t)(y0 + 3) * WW + x0;

        for (int yy = 0; yy < ROWS - 1; yy++) {
            float4 pa = *(const float4*)rp;
            float2 pb = hi_ok ? *(const float2*)(rp + 4) : make_float2(0.f, 0.f);
            rp += WW;

            const float v0[6] = {a0.x, a0.y, a0.z, a0.w, b0.x, b0.y};
            const float v1[6] = {a1.x, a1.y, a1.z, a1.w, b1.x, b1.y};
            const float v2[6] = {a2.x, a2.y, a2.z, a2.w, b2.x, b2.y};

            float acc[4];
#pragma unroll
            for (int j = 0; j < 4; j++) {
                float s = v0[j] * wt[0];
                s = fmaf(v0[j + 1], wt[1], s);
                s = fmaf(v0[j + 2], wt[2], s);
                s = fmaf(v1[j],     wt[3], s);
                s = fmaf(v1[j + 1], wt[4], s);
                s = fmaf(v1[j + 2], wt[5], s);
                s = fmaf(v2[j],     wt[6], s);
                s = fmaf(v2[j + 1], wt[7], s);
                s = fmaf(v2[j + 2], wt[8], s);
                acc[j] = s;
            }

            float* orow = op + (size_t)(y0 + yy) * OWD + x0;
            __stcs((float2*)orow, make_float2(acc[0], acc[1]));
            if (hi_ok)
                __stcs((float2*)(orow + 2), make_float2(acc[2], acc[3]));

            a0 = a1; b0 = b1;
            a1 = a2; b1 = b2;
            a2 = pa; b2 = pb;
        }

        // ---- peeled last row (yy = ROWS-1): compute only, no prefetch ----
        {
            const float v0[6] = {a0.x, a0.y, a0.z, a0.w, b0.x, b0.y};
            const float v1[6] = {a1.x, a1.y, a1.z, a1.w, b1.x, b1.y};
            const float v2[6] = {a2.x, a2.y, a2.z, a2.w, b2.x, b2.y};

            float acc[4];
#pragma unroll
            for (int j = 0; j < 4; j++) {
                float s = v0[j] * wt[0];
                s = fmaf(v0[j + 1], wt[1], s);
                s = fmaf(v0[j + 2], wt[2], s);
                s = fmaf(v1[j],     wt[3], s);
                s = fmaf(v1[j + 1], wt[4], s);
                s = fmaf(v1[j + 2], wt[5], s);
                s = fmaf(v2[j],     wt[6], s);
                s = fmaf(v2[j + 1], wt[7], s);
                s = fmaf(v2[j + 2], wt[8], s);
                acc[j] = s;
            }

            float* orow = op + (size_t)(y0 + ROWS - 1) * OWD + x0;
            __stcs((float2*)orow, make_float2(acc[0], acc[1]));
            if (hi_ok)
                __stcs((float2*)(orow + 2), make_float2(acc[2], acc[3]));
        }
    } else {
        // ================= odd tiles: sweep bottom -> top ==================
        // Serpentine: boundary rows shared with neighbor tiles are read in the
        // same execution phase -> second read hits L2, not DRAM.
        float4 a0, a1, a2;
        float2 b0, b1, b2;
        {
            const float* r = xp + (size_t)(y0 + ROWS - 1) * WW + x0;   // rows y0+29..y0+31
            a0 = *(const float4*)(r);
            a1 = *(const float4*)(r + WW);
            a2 = *(const float4*)(r + 2 * WW);
            if (hi_ok) {
                b0 = *(const float2*)(r + 4);
                b1 = *(const float2*)(r + WW + 4);
                b2 = *(const float2*)(r + 2 * WW + 4);
            } else {
                b0 = b1 = b2 = make_float2(0.f, 0.f);
            }
        }

        // Prefetch row y0+yy-1; odd tiles have y0 >= 30 so the final prefetch
        // (row y0-1 >= 29) is always in-bounds: clamp-free.
        const float* rp = xp + (size_t)(y0 + ROWS - 2) * WW + x0;

        for (int yy = ROWS - 1; yy >= 0; yy--) {
            float4 pa = *(const float4*)rp;
            float2 pb = hi_ok ? *(const float2*)(rp + 4) : make_float2(0.f, 0.f);
            rp -= WW;

            const float v0[6] = {a0.x, a0.y, a0.z, a0.w, b0.x, b0.y};
            const float v1[6] = {a1.x, a1.y, a1.z, a1.w, b1.x, b1.y};
            const float v2[6] = {a2.x, a2.y, a2.z, a2.w, b2.x, b2.y};

            float acc[4];
#pragma unroll
            for (int j = 0; j < 4; j++) {
                float s = v0[j] * wt[0];
                s = fmaf(v0[j + 1], wt[1], s);
                s = fmaf(v0[j + 2], wt[2], s);
                s = fmaf(v1[j],     wt[3], s);
                s = fmaf(v1[j + 1], wt[4], s);
                s = fmaf(v1[j + 2], wt[5], s);
                s = fmaf(v2[j],     wt[6], s);
                s = fmaf(v2[j + 1], wt[7], s);
                s = fmaf(v2[j + 2], wt[8], s);
                acc[j] = s;
            }

            float* orow = op + (size_t)(y0 + yy) * OWD + x0;
            __stcs((float2*)orow, make_float2(acc[0], acc[1]));
            if (hi_ok)
                __stcs((float2*)(orow + 2), make_float2(acc[2], acc[3]));

            // rotate window upward
            a2 = a1; b2 = b1;
            a1 = a0; b1 = b0;
            a0 = pa; b0 = pb;
        }
    }
}

extern "C" void kernel_launch(void* const* d_in, const int* in_sizes, int n_in,
                              void* d_out, int out_size)
{
    const float* x   = (const float*)d_in[0];
    const float* wgt = (const float*)d_in[1];
    float*       out = (float*)d_out;

    dim3 grid(NTILES, 16 * CCH);   // 17 row tiles (fast) x 1024 (n,c) planes
    dwconv3x3_kernel<<<grid, 128>>>(x, wgt, out);
}

// round 15
// speedup vs baseline: 1.0632x; 1.0632x over previous
#include <cuda_runtime.h>

// Depthwise 3x3 conv, stride 1, VALID, fp32.
// x: (16, 64, 512, 512), weight: (64, 3, 3), out: (16, 64, 510, 510)
//
// FINAL CONFIG (mapped pareto point over 13 rounds):
//  - 128 thr/CTA, 12 CTAs/SM, 40 regs (any lower reg budget spills the window:
//    occ13 -> 32 regs -> 340us; occ14 -> 32 regs -> 380us)
//  - ROWS=30 tiles (tail-wave optimum of ceil(N/slots)*(2R+2))
//  - serpentine tile sweep (odd tiles bottom-up): inter-tile halo hits L2 (-3.6%)
//  - register sliding window, compiler-unrolled y-loop (unroll-pin costs +38us)
//  - default-cached loads (L1 serves the 1.5x halo; .cs loads cost +60us)
//  - __stcs streaming stores (output is write-once)

#define CCH    64
#define HH     512
#define WW     512
#define OHT    510
#define OWD    510
#define ROWS   30     // output rows per CTA (17 * 30 = 510)
#define NTILES 17

__global__ __launch_bounds__(128, 12)
void dwconv3x3_kernel(const float* __restrict__ x,
                      const float* __restrict__ wgt,
                      float* __restrict__ out)
{
    const int tile = blockIdx.x;          // 0..16 (fast-varying: same-plane tiles co-wave)
    const int nc   = blockIdx.y;          // n*64 + c
    const int c    = nc & (CCH - 1);

    const float* xp = x   + (size_t)nc * HH * WW;
    float*       op = out + (size_t)nc * OHT * OWD;

    float wt[9];
#pragma unroll
    for (int i = 0; i < 9; i++) wt[i] = __ldg(wgt + c * 9 + i);

    const int  tid   = threadIdx.x;       // 0..127
    const int  x0    = tid * 4;           // output cols x0..x0+3
    const bool hi_ok = (tid < 127);       // tid 127: cols 510/511 invalid, halo OOB
    const int  y0    = tile * ROWS;

    if (!(tile & 1)) {
        // ================= even tiles: sweep top -> bottom =================
        float4 a0, a1, a2;
        float2 b0, b1, b2;
        {
            const float* r = xp + (size_t)y0 * WW + x0;
            a0 = *(const float4*)(r);
            a1 = *(const float4*)(r + WW);
            a2 = *(const float4*)(r + 2 * WW);
            if (hi_ok) {
                b0 = *(const float2*)(r + 4);
                b1 = *(const float2*)(r + WW + 4);
                b2 = *(const float2*)(r + 2 * WW + 4);
            } else {
                b0 = b1 = b2 = make_float2(0.f, 0.f);
            }
        }

        // For yy < ROWS-1 the prefetch row y0+yy+3 <= y0+31 <= 511 is ALWAYS
        // in-bounds (y0 <= 480) -> clamp-free hot loop; last iteration peeled
        // below with no prefetch.
        const float* rp = xp + (size_t)(y0 + 3) * WW + x0;

        for (int yy = 0; yy < ROWS - 1; yy++) {
            float4 pa = *(const float4*)rp;
            float2 pb = hi_ok ? *(const float2*)(rp + 4) : make_float2(0.f, 0.f);
            rp += WW;

            const float v0[6] = {a0.x, a0.y, a0.z, a0.w, b0.x, b0.y};
            const float v1[6] = {a1.x, a1.y, a1.z, a1.w, b1.x, b1.y};
            const float v2[6] = {a2.x, a2.y, a2.z, a2.w, b2.x, b2.y};

            float acc[4];
#pragma unroll
            for (int j = 0; j < 4; j++) {
                float s = v0[j] * wt[0];
                s = fmaf(v0[j + 1], wt[1], s);
                s = fmaf(v0[j + 2], wt[2], s);
                s = fmaf(v1[j],     wt[3], s);
                s = fmaf(v1[j + 1], wt[4], s);
                s = fmaf(v1[j + 2], wt[5], s);
                s = fmaf(v2[j],     wt[6], s);
                s = fmaf(v2[j + 1], wt[7], s);
                s = fmaf(v2[j + 2], wt[8], s);
                acc[j] = s;
            }

            float* orow = op + (size_t)(y0 + yy) * OWD + x0;
            __stcs((float2*)orow, make_float2(acc[0], acc[1]));
            if (hi_ok)
                __stcs((float2*)(orow + 2), make_float2(acc[2], acc[3]));

            a0 = a1; b0 = b1;
            a1 = a2; b1 = b2;
            a2 = pa; b2 = pb;
        }

        // ---- peeled last row (yy = ROWS-1): compute only, no prefetch ----
        {
            const float v0[6] = {a0.x, a0.y, a0.z, a0.w, b0.x, b0.y};
            const float v1[6] = {a1.x, a1.y, a1.z, a1.w, b1.x, b1.y};
            const float v2[6] = {a2.x, a2.y, a2.z, a2.w, b2.x, b2.y};

            float acc[4];
#pragma unroll
            for (int j = 0; j < 4; j++) {
                float s = v0[j] * wt[0];
                s = fmaf(v0[j + 1], wt[1], s);
                s = fmaf(v0[j + 2], wt[2], s);
                s = fmaf(v1[j],     wt[3], s);
                s = fmaf(v1[j + 1], wt[4], s);
                s = fmaf(v1[j + 2], wt[5], s);
                s = fmaf(v2[j],     wt[6], s);
                s = fmaf(v2[j + 1], wt[7], s);
                s = fmaf(v2[j + 2], wt[8], s);
                acc[j] = s;
            }

            float* orow = op + (size_t)(y0 + ROWS - 1) * OWD + x0;
            __stcs((float2*)orow, make_float2(acc[0], acc[1]));
            if (hi_ok)
                __stcs((float2*)(orow + 2), make_float2(acc[2], acc[3]));
        }
    } else {
        // ================= odd tiles: sweep bottom -> top ==================
        // Serpentine: boundary rows shared with neighbor tiles are read in the
        // same execution phase -> second read hits L2, not DRAM.
        float4 a0, a1, a2;
        float2 b0, b1, b2;
        {
            const float* r = xp + (size_t)(y0 + ROWS - 1) * WW + x0;   // rows y0+29..y0+31
            a0 = *(const float4*)(r);
            a1 = *(const float4*)(r + WW);
            a2 = *(const float4*)(r + 2 * WW);
            if (hi_ok) {
                b0 = *(const float2*)(r + 4);
                b1 = *(const float2*)(r + WW + 4);
                b2 = *(const float2*)(r + 2 * WW + 4);
            } else {
                b0 = b1 = b2 = make_float2(0.f, 0.f);
            }
        }

        // Prefetch row y0+yy-1; odd tiles have y0 >= 30 so the final prefetch
        // (row y0-1 >= 29) is always in-bounds: clamp-free.
        const float* rp = xp + (size_t)(y0 + ROWS - 2) * WW + x0;

        for (int yy = ROWS - 1; yy >= 0; yy--) {
            float4 pa = *(const float4*)rp;
            float2 pb = hi_ok ? *(const float2*)(rp + 4) : make_float2(0.f, 0.f);
            rp -= WW;

            const float v0[6] = {a0.x, a0.y, a0.z, a0.w, b0.x, b0.y};
            const float v1[6] = {a1.x, a1.y, a1.z, a1.w, b1.x, b1.y};
            const float v2[6] = {a2.x, a2.y, a2.z, a2.w, b2.x, b2.y};

            float acc[4];
#pragma unroll
            for (int j = 0; j < 4; j++) {
                float s = v0[j] * wt[0];
                s = fmaf(v0[j + 1], wt[1], s);
                s = fmaf(v0[j + 2], wt[2], s);
                s = fmaf(v1[j],     wt[3], s);
                s = fmaf(v1[j + 1], wt[4], s);
                s = fmaf(v1[j + 2], wt[5], s);
                s = fmaf(v2[j],     wt[6], s);
                s = fmaf(v2[j + 1], wt[7], s);
                s = fmaf(v2[j + 2], wt[8], s);
                acc[j] = s;
            }

            float* orow = op + (size_t)(y0 + yy) * OWD + x0;
            __stcs((float2*)orow, make_float2(acc[0], acc[1]));
            if (hi_ok)
                __stcs((float2*)(orow + 2), make_float2(acc[2], acc[3]));

            // rotate window upward
            a2 = a1; b2 = b1;
            a1 = a0; b1 = b0;
            a0 = pa; b0 = pb;
        }
    }
}

extern "C" void kernel_launch(void* const* d_in, const int* in_sizes, int n_in,
                              void* d_out, int out_size)
{
    const float* x   = (const float*)d_in[0];
    const float* wgt = (const float*)d_in[1];
    float*       out = (float*)d_out;

    dim3 grid(NTILES, 16 * CCH);   // 17 row tiles (fast) x 1024 (n,c) planes
    dwconv3x3_kernel<<<grid, 128>>>(x, wgt, out);
}